// round 5
// baseline (speedup 1.0000x reference)
#include <cuda_runtime.h>

#define VOCAB 100000
#define BATCH 2048
#define SEQ   50
#define HID   256
#define KIN   512

__device__ __forceinline__ float lky(float v) {
    return (v > 0.f) ? v : 0.2f * v;
}

// ---------------------------------------------------------------------------
// Block types:
//   A: beo GEMM (BM=16, BN=256 full width, BK=32) + in-block epilogue. 128 blks
//   B: bow gather (4 rows) + in-block epilogue.                        512 blks
// Interleaved: blockIdx % 5 == 0 -> A, else B.  Grid = 640, 256 threads.
// ---------------------------------------------------------------------------
#define AM   16
#define ABK  32
#define NA   (BATCH / AM)          // 128
#define BR   4                      // bow rows per block
#define NB   (BATCH / BR)           // 512
#define NBLK (NA + NB)              // 640

union SmemU {
    struct {                                    // A: GEMM tiles
        float As[AM][ABK + 4];
        float Bs[ABK][HID];
    } g;
    float Hs[AM][HID + 4];                      // A: hidden tile (epilogue)
    struct {                                    // B: bow scratch
        unsigned int wbuf[BR * SEQ];
        int   toks[BR][SEQ];
        float keep[BR][SEQ];
        float hid[BR][HID];
        int   is64;
    } b;
};

__global__ __launch_bounds__(256) void fused_all_kernel(
    const unsigned int* __restrict__ s_words,
    const float* __restrict__ Wh,     const float* __restrict__ bh,
    const float* __restrict__ X,      const float* __restrict__ Wb,
    const float* __restrict__ bb_,
    const float* __restrict__ We_bow, const float* __restrict__ be_bow,
    const float* __restrict__ Wp_bow, const float* __restrict__ bp_bow,
    const float* __restrict__ We_beo, const float* __restrict__ be_beo,
    const float* __restrict__ Wp_beo, const float* __restrict__ bp_beo,
    float* __restrict__ out)
{
    __shared__ SmemU sm;
    const int tid = threadIdx.x;
    const int idx = blockIdx.x;

    if (idx % 5 == 0) {
        // ==================== Type A: beo GEMM + epilogue ====================
        const int m0 = (idx / 5) * AM;
        const int tx = tid & 31;     // 32 col groups * 8 cols
        const int ty = tid >> 5;     // 8 row groups * 2 rows

        unsigned long long acc[2][4];
        #pragma unroll
        for (int r = 0; r < 2; r++)
            #pragma unroll
            for (int c = 0; c < 4; c++) acc[r][c] = 0ull;

        for (int k0 = 0; k0 < KIN; k0 += ABK) {
            if (tid < 128) {                       // A tile: 16x32 = 128 float4
                int r = tid >> 3, q = tid & 7;
                *(float4*)&sm.g.As[r][q * 4] =
                    *(const float4*)&X[(m0 + r) * KIN + k0 + q * 4];
            }
            #pragma unroll
            for (int f = tid; f < ABK * HID / 4; f += 256) {  // B tile 32x256
                int kr = f >> 6, nq = f & 63;
                *(float4*)&sm.g.Bs[kr][nq * 4] =
                    *(const float4*)&Wb[(k0 + kr) * HID + nq * 4];
            }
            __syncthreads();

            #pragma unroll
            for (int k = 0; k < ABK; k++) {
                float4 b0 = *(const float4*)&sm.g.Bs[k][tx * 8];
                float4 b1 = *(const float4*)&sm.g.Bs[k][tx * 8 + 4];
                unsigned long long pb0, pb1, pb2, pb3;
                asm("mov.b64 %0, {%1, %2};" : "=l"(pb0) : "f"(b0.x), "f"(b0.y));
                asm("mov.b64 %0, {%1, %2};" : "=l"(pb1) : "f"(b0.z), "f"(b0.w));
                asm("mov.b64 %0, {%1, %2};" : "=l"(pb2) : "f"(b1.x), "f"(b1.y));
                asm("mov.b64 %0, {%1, %2};" : "=l"(pb3) : "f"(b1.z), "f"(b1.w));
                #pragma unroll
                for (int r = 0; r < 2; r++) {
                    float av = sm.g.As[ty * 2 + r][k];
                    unsigned long long pa;
                    asm("mov.b64 %0, {%1, %1};" : "=l"(pa) : "f"(av));
                    asm("fma.rn.f32x2 %0, %1, %2, %0;" : "+l"(acc[r][0]) : "l"(pa), "l"(pb0));
                    asm("fma.rn.f32x2 %0, %1, %2, %0;" : "+l"(acc[r][1]) : "l"(pa), "l"(pb1));
                    asm("fma.rn.f32x2 %0, %1, %2, %0;" : "+l"(acc[r][2]) : "l"(pa), "l"(pb2));
                    asm("fma.rn.f32x2 %0, %1, %2, %0;" : "+l"(acc[r][3]) : "l"(pa), "l"(pb3));
                }
            }
            __syncthreads();
        }

        // bias + leaky, deposit hidden tile into shared
        {
            const float4 be0 = *(const float4*)&bb_[tx * 8];
            const float4 be1 = *(const float4*)&bb_[tx * 8 + 4];
            #pragma unroll
            for (int r = 0; r < 2; r++) {
                float o[8];
                asm("mov.b64 {%0, %1}, %2;" : "=f"(o[0]), "=f"(o[1]) : "l"(acc[r][0]));
                asm("mov.b64 {%0, %1}, %2;" : "=f"(o[2]), "=f"(o[3]) : "l"(acc[r][1]));
                asm("mov.b64 {%0, %1}, %2;" : "=f"(o[4]), "=f"(o[5]) : "l"(acc[r][2]));
                asm("mov.b64 {%0, %1}, %2;" : "=f"(o[6]), "=f"(o[7]) : "l"(acc[r][3]));
                *(float4*)&sm.Hs[ty * 2 + r][tx * 8] =
                    make_float4(lky(o[0] + be0.x), lky(o[1] + be0.y),
                                lky(o[2] + be0.z), lky(o[3] + be0.w));
                *(float4*)&sm.Hs[ty * 2 + r][tx * 8 + 4] =
                    make_float4(lky(o[4] + be1.x), lky(o[5] + be1.y),
                                lky(o[6] + be1.z), lky(o[7] + be1.w));
            }
        }
        __syncthreads();

        // ---- embd: 16 rows x 64 cols; thread = (row, 4 cols), 4 FMA2 chains
        {
            const int rw = tid >> 4;
            const int cg = tid & 15;
            unsigned long long eA0 = 0ull, eA1 = 0ull, eB0 = 0ull, eB1 = 0ull;
            #pragma unroll 4
            for (int k = 0; k < HID; k += 2) {
                float h0 = sm.Hs[rw][k];
                float h1 = sm.Hs[rw][k + 1];
                unsigned long long w00 = *(const unsigned long long*)&We_beo[k * 64 + cg * 4];
                unsigned long long w01 = *(const unsigned long long*)&We_beo[k * 64 + cg * 4 + 2];
                unsigned long long w10 = *(const unsigned long long*)&We_beo[(k + 1) * 64 + cg * 4];
                unsigned long long w11 = *(const unsigned long long*)&We_beo[(k + 1) * 64 + cg * 4 + 2];
                unsigned long long ph0, ph1;
                asm("mov.b64 %0, {%1, %1};" : "=l"(ph0) : "f"(h0));
                asm("mov.b64 %0, {%1, %1};" : "=l"(ph1) : "f"(h1));
                asm("fma.rn.f32x2 %0, %1, %2, %0;" : "+l"(eA0) : "l"(ph0), "l"(w00));
                asm("fma.rn.f32x2 %0, %1, %2, %0;" : "+l"(eA1) : "l"(ph0), "l"(w01));
                asm("fma.rn.f32x2 %0, %1, %2, %0;" : "+l"(eB0) : "l"(ph1), "l"(w10));
                asm("fma.rn.f32x2 %0, %1, %2, %0;" : "+l"(eB1) : "l"(ph1), "l"(w11));
            }
            float a0, a1, a2, a3, c0, c1, c2, c3;
            asm("mov.b64 {%0, %1}, %2;" : "=f"(a0), "=f"(a1) : "l"(eA0));
            asm("mov.b64 {%0, %1}, %2;" : "=f"(a2), "=f"(a3) : "l"(eA1));
            asm("mov.b64 {%0, %1}, %2;" : "=f"(c0), "=f"(c1) : "l"(eB0));
            asm("mov.b64 {%0, %1}, %2;" : "=f"(c2), "=f"(c3) : "l"(eB1));
            const float4 be = *(const float4*)&be_beo[cg * 4];
            *(float4*)&out[BATCH * 64 + (m0 + rw) * 64 + cg * 4] =
                make_float4(a0 + c0 + be.x, a1 + c1 + be.y,
                            a2 + c2 + be.z, a3 + c3 + be.w);
        }

        // ---- pred: 16 rows x 5 cols = 80 threads, 4 fmaf chains
        if (tid < AM * 5) {
            int r = tid / 5, j = tid - r * 5;
            float a0 = 0.f, a1 = 0.f, a2 = 0.f, a3 = 0.f;
            #pragma unroll 4
            for (int k = 0; k < HID; k += 4) {
                a0 = fmaf(sm.Hs[r][k + 0], Wp_beo[(k + 0) * 5 + j], a0);
                a1 = fmaf(sm.Hs[r][k + 1], Wp_beo[(k + 1) * 5 + j], a1);
                a2 = fmaf(sm.Hs[r][k + 2], Wp_beo[(k + 2) * 5 + j], a2);
                a3 = fmaf(sm.Hs[r][k + 3], Wp_beo[(k + 3) * 5 + j], a3);
            }
            out[BATCH * 128 + BATCH * 5 + (m0 + r) * 5 + j] =
                (a0 + a1) + (a2 + a3) + bp_beo[j];
        }
    } else {
        // ==================== Type B: bow gather + epilogue ==================
        const int kb    = idx - idx / 5 - 1;          // 0..511
        const int row0  = kb * BR;
        const int wbase = kb * (BR * SEQ);

        if (tid < BR * SEQ) sm.b.wbuf[tid] = s_words[wbase + tid];
        __syncthreads();

        if (tid == 0) {
            int all0 = 1;
            #pragma unroll
            for (int i = 1; i < BR * SEQ; i += 2) all0 &= (sm.b.wbuf[i] == 0u);
            sm.b.is64 = all0;
        }
        __syncthreads();

        const int is64 = sm.b.is64;
        if (tid < BR * SEQ) {
            int r = tid / SEQ, j = tid - r * SEQ;
            sm.b.toks[r][j] = is64 ? (int)s_words[2 * (wbase + tid)]
                                   : (int)sm.b.wbuf[tid];
        }
        __syncthreads();

        if (tid < BR * SEQ) {
            int r = tid / SEQ, j = tid - r * SEQ;
            int t = sm.b.toks[r][j];
            float k = 1.0f;
            for (int j2 = 0; j2 < j; j2++)
                if (sm.b.toks[r][j2] == t) { k = 0.0f; break; }
            sm.b.keep[r][j] = k;
        }
        __syncthreads();

        // gather: 4 rows x 64 col-threads (float4), 4 rotating accumulators
        {
            const int r  = tid >> 6;
            const int c4 = (tid & 63) * 4;
            const float* __restrict__ Wc = Wh + c4;

            float4 sa[4];
            #pragma unroll
            for (int q = 0; q < 4; q++) sa[q] = make_float4(0.f, 0.f, 0.f, 0.f);

            #pragma unroll
            for (int i = 0; i < 48; i += 4) {
                const float4 v0 = *(const float4*)(Wc + sm.b.toks[r][i + 0] * HID);
                const float4 v1 = *(const float4*)(Wc + sm.b.toks[r][i + 1] * HID);
                const float4 v2 = *(const float4*)(Wc + sm.b.toks[r][i + 2] * HID);
                const float4 v3 = *(const float4*)(Wc + sm.b.toks[r][i + 3] * HID);
                const float k0 = sm.b.keep[r][i + 0], k1 = sm.b.keep[r][i + 1];
                const float k2 = sm.b.keep[r][i + 2], k3 = sm.b.keep[r][i + 3];
                sa[0].x = fmaf(k0, v0.x, sa[0].x); sa[0].y = fmaf(k0, v0.y, sa[0].y);
                sa[0].z = fmaf(k0, v0.z, sa[0].z); sa[0].w = fmaf(k0, v0.w, sa[0].w);
                sa[1].x = fmaf(k1, v1.x, sa[1].x); sa[1].y = fmaf(k1, v1.y, sa[1].y);
                sa[1].z = fmaf(k1, v1.z, sa[1].z); sa[1].w = fmaf(k1, v1.w, sa[1].w);
                sa[2].x = fmaf(k2, v2.x, sa[2].x); sa[2].y = fmaf(k2, v2.y, sa[2].y);
                sa[2].z = fmaf(k2, v2.z, sa[2].z); sa[2].w = fmaf(k2, v2.w, sa[2].w);
                sa[3].x = fmaf(k3, v3.x, sa[3].x); sa[3].y = fmaf(k3, v3.y, sa[3].y);
                sa[3].z = fmaf(k3, v3.z, sa[3].z); sa[3].w = fmaf(k3, v3.w, sa[3].w);
            }
            {   // tail 48, 49
                const float4 v0 = *(const float4*)(Wc + sm.b.toks[r][48] * HID);
                const float4 v1 = *(const float4*)(Wc + sm.b.toks[r][49] * HID);
                const float k0 = sm.b.keep[r][48], k1 = sm.b.keep[r][49];
                sa[0].x = fmaf(k0, v0.x, sa[0].x); sa[0].y = fmaf(k0, v0.y, sa[0].y);
                sa[0].z = fmaf(k0, v0.z, sa[0].z); sa[0].w = fmaf(k0, v0.w, sa[0].w);
                sa[1].x = fmaf(k1, v1.x, sa[1].x); sa[1].y = fmaf(k1, v1.y, sa[1].y);
                sa[1].z = fmaf(k1, v1.z, sa[1].z); sa[1].w = fmaf(k1, v1.w, sa[1].w);
            }
            const float4 bv = *(const float4*)(bh + c4);
            sm.b.hid[r][c4 + 0] = lky((sa[0].x + sa[1].x) + (sa[2].x + sa[3].x) + bv.x);
            sm.b.hid[r][c4 + 1] = lky((sa[0].y + sa[1].y) + (sa[2].y + sa[3].y) + bv.y);
            sm.b.hid[r][c4 + 2] = lky((sa[0].z + sa[1].z) + (sa[2].z + sa[3].z) + bv.z);
            sm.b.hid[r][c4 + 3] = lky((sa[0].w + sa[1].w) + (sa[2].w + sa[3].w) + bv.w);
        }
        __syncthreads();

        // ---- embd: 4 rows x 64 cols; one output/thread, 4 fmaf chains
        {
            const int r = tid >> 6;
            const int c = tid & 63;
            float a0 = 0.f, a1 = 0.f, a2 = 0.f, a3 = 0.f;
            #pragma unroll 4
            for (int k = 0; k < HID; k += 4) {
                a0 = fmaf(sm.b.hid[r][k + 0], We_bow[(k + 0) * 64 + c], a0);
                a1 = fmaf(sm.b.hid[r][k + 1], We_bow[(k + 1) * 64 + c], a1);
                a2 = fmaf(sm.b.hid[r][k + 2], We_bow[(k + 2) * 64 + c], a2);
                a3 = fmaf(sm.b.hid[r][k + 3], We_bow[(k + 3) * 64 + c], a3);
            }
            out[(row0 + r) * 64 + c] = (a0 + a1) + (a2 + a3) + be_bow[c];
        }

        // ---- pred: 4 rows x 5 cols = 20 threads
        if (tid < BR * 5) {
            int r = tid / 5, j = tid - r * 5;
            float a0 = 0.f, a1 = 0.f, a2 = 0.f, a3 = 0.f;
            #pragma unroll 4
            for (int k = 0; k < HID; k += 4) {
                a0 = fmaf(sm.b.hid[r][k + 0], Wp_bow[(k + 0) * 5 + j], a0);
                a1 = fmaf(sm.b.hid[r][k + 1], Wp_bow[(k + 1) * 5 + j], a1);
                a2 = fmaf(sm.b.hid[r][k + 2], Wp_bow[(k + 2) * 5 + j], a2);
                a3 = fmaf(sm.b.hid[r][k + 3], Wp_bow[(k + 3) * 5 + j], a3);
            }
            out[BATCH * 128 + (row0 + r) * 5 + j] = (a0 + a1) + (a2 + a3) + bp_bow[j];
        }
    }
}

// ============================================================================
extern "C" void kernel_launch(void* const* d_in, const int* in_sizes, int n_in,
                              void* d_out, int out_size)
{
    const unsigned int* s_words = (const unsigned int*)d_in[0];
    const float* x        = (const float*)d_in[1];
    const float* W_bow_h  = (const float*)d_in[2];
    const float* b_bow_h  = (const float*)d_in[3];
    const float* W_bow_p  = (const float*)d_in[4];
    const float* b_bow_p  = (const float*)d_in[5];
    const float* W_bow_e  = (const float*)d_in[6];
    const float* b_bow_e  = (const float*)d_in[7];
    const float* W_beo_h  = (const float*)d_in[8];
    const float* b_beo_h  = (const float*)d_in[9];
    const float* W_beo_p  = (const float*)d_in[10];
    const float* b_beo_p  = (const float*)d_in[11];
    const float* W_beo_e  = (const float*)d_in[12];
    const float* b_beo_e  = (const float*)d_in[13];
    float* out = (float*)d_out;

    fused_all_kernel<<<NBLK, 256>>>(
        s_words, W_bow_h, b_bow_h,
        x, W_beo_h, b_beo_h,
        W_bow_e, b_bow_e, W_bow_p, b_bow_p,
        W_beo_e, b_beo_e, W_beo_p, b_beo_p,
        out);
}

// round 6
// speedup vs baseline: 1.8873x; 1.8873x over previous
#include <cuda_runtime.h>

#define VOCAB 100000
#define BATCH 2048
#define SEQ   50
#define HID   256
#define KIN   512

// ---------------- scratch (device globals; no allocation allowed) ----------
__device__ float g_bow_h[BATCH * HID];
__device__ float g_beo_h[BATCH * HID];

__device__ __forceinline__ float lky(float v) {
    return (v > 0.f) ? v : 0.2f * v;
}

// ============================================================================
// Fused kernel: blocks [0, K2_BLOCKS) do the beo GEMM; blocks
// [K2_BLOCKS, K2_BLOCKS + K1_BLOCKS) do the bow gather. 256 threads each.
// (identical to round 4 — known good)
// ============================================================================
#define BM 64
#define BN 64
#define BK 32
#define K2_BLOCKS ((BATCH / BM) * (HID / BN))   // 128
#define K1_ROWS_PER_BLK 2
#define K1_BLOCKS (BATCH / K1_ROWS_PER_BLK)     // 1024

union SmemU {
    struct {                       // GEMM tiles
        float As[BM][BK + 4];
        float Bs[BK][BN];
    } g;
    struct {                       // bow gather scratch
        unsigned int wbuf[K1_ROWS_PER_BLK * SEQ];
        int   toks[K1_ROWS_PER_BLK][SEQ];
        float keep[K1_ROWS_PER_BLK][SEQ];
        float part[K1_ROWS_PER_BLK][HID];
        int   is64;
    } b;
};

__global__ __launch_bounds__(256) void fused_hidden_kernel(
    const unsigned int* __restrict__ s_words,
    const float* __restrict__ Wh,    const float* __restrict__ bh,
    const float* __restrict__ X,     const float* __restrict__ W,
    const float* __restrict__ bias)
{
    __shared__ SmemU sm;
    const int tid = threadIdx.x;

    if (blockIdx.x < K2_BLOCKS) {
        // ------------------------- beo GEMM path ---------------------------
        const int bx = blockIdx.x;
        const int m0 = (bx >> 2) * BM;
        const int n0 = (bx & 3) * BN;
        const int tx = tid & 15;
        const int ty = tid >> 4;

        unsigned long long acc[4][2];
        #pragma unroll
        for (int r = 0; r < 4; r++) { acc[r][0] = 0ull; acc[r][1] = 0ull; }

        for (int k0 = 0; k0 < KIN; k0 += BK) {
            #pragma unroll
            for (int f = tid; f < BM * BK / 4; f += 256) {
                int r = f >> 3, q = f & 7;
                *(float4*)&sm.g.As[r][q * 4] =
                    *(const float4*)&X[(m0 + r) * KIN + k0 + q * 4];
            }
            #pragma unroll
            for (int f = tid; f < BK * BN / 4; f += 256) {
                int kr = f >> 4, nq = f & 15;
                *(float4*)&sm.g.Bs[kr][nq * 4] =
                    *(const float4*)&W[(k0 + kr) * HID + n0 + nq * 4];
            }
            __syncthreads();

            #pragma unroll
            for (int k = 0; k < BK; k++) {
                float4 bv = *(const float4*)&sm.g.Bs[k][tx * 4];
                unsigned long long pb0, pb1;
                asm("mov.b64 %0, {%1, %2};" : "=l"(pb0) : "f"(bv.x), "f"(bv.y));
                asm("mov.b64 %0, {%1, %2};" : "=l"(pb1) : "f"(bv.z), "f"(bv.w));
                #pragma unroll
                for (int r = 0; r < 4; r++) {
                    float av = sm.g.As[ty * 4 + r][k];
                    unsigned long long pa;
                    asm("mov.b64 %0, {%1, %1};" : "=l"(pa) : "f"(av));
                    asm("fma.rn.f32x2 %0, %1, %2, %0;" : "+l"(acc[r][0]) : "l"(pa), "l"(pb0));
                    asm("fma.rn.f32x2 %0, %1, %2, %0;" : "+l"(acc[r][1]) : "l"(pa), "l"(pb1));
                }
            }
            __syncthreads();
        }

        const float4 bb = *(const float4*)&bias[n0 + tx * 4];
        #pragma unroll
        for (int r = 0; r < 4; r++) {
            float o0, o1, o2, o3;
            asm("mov.b64 {%0, %1}, %2;" : "=f"(o0), "=f"(o1) : "l"(acc[r][0]));
            asm("mov.b64 {%0, %1}, %2;" : "=f"(o2), "=f"(o3) : "l"(acc[r][1]));
            *(float4*)&g_beo_h[(m0 + ty * 4 + r) * HID + n0 + tx * 4] =
                make_float4(lky(o0 + bb.x), lky(o1 + bb.y),
                            lky(o2 + bb.z), lky(o3 + bb.w));
        }
    } else {
        // ------------------------- bow gather path -------------------------
        const int kb    = blockIdx.x - K2_BLOCKS;
        const int wbase = kb * (K1_ROWS_PER_BLK * SEQ);

        if (tid < K1_ROWS_PER_BLK * SEQ) sm.b.wbuf[tid] = s_words[wbase + tid];
        __syncthreads();

        if (tid == 0) {
            int all0 = 1;
            #pragma unroll
            for (int i = 1; i < K1_ROWS_PER_BLK * SEQ; i += 2)
                all0 &= (sm.b.wbuf[i] == 0u);
            sm.b.is64 = all0;
        }
        __syncthreads();

        const int is64 = sm.b.is64;
        if (tid < K1_ROWS_PER_BLK * SEQ) {
            int r = tid / SEQ, j = tid - r * SEQ;
            sm.b.toks[r][j] = is64 ? (int)s_words[2 * (wbase + tid)]
                                   : (int)sm.b.wbuf[tid];
        }
        __syncthreads();

        if (tid < K1_ROWS_PER_BLK * SEQ) {
            int r = tid / SEQ, j = tid - r * SEQ;
            int t = sm.b.toks[r][j];
            float k = 1.0f;
            for (int j2 = 0; j2 < j; j2++)
                if (sm.b.toks[r][j2] == t) { k = 0.0f; break; }
            sm.b.keep[r][j] = k;
        }
        __syncthreads();

        const int r    = tid >> 7;
        const int h    = (tid >> 6) & 1;
        const int c4   = (tid & 63) * 4;
        const int jb   = h * (SEQ / 2);
        const float* __restrict__ Wc = Wh + c4;

        float4 sa[4];
        #pragma unroll
        for (int q = 0; q < 4; q++) sa[q] = make_float4(0.f, 0.f, 0.f, 0.f);

        #pragma unroll
        for (int i = 0; i < SEQ / 2; i++) {
            const float4 v = *(const float4*)(Wc + sm.b.toks[r][jb + i] * HID);
            const float  kf = sm.b.keep[r][jb + i];
            float4& a = sa[i & 3];
            a.x = fmaf(kf, v.x, a.x); a.y = fmaf(kf, v.y, a.y);
            a.z = fmaf(kf, v.z, a.z); a.w = fmaf(kf, v.w, a.w);
        }
        float4 t;
        t.x = (sa[0].x + sa[1].x) + (sa[2].x + sa[3].x);
        t.y = (sa[0].y + sa[1].y) + (sa[2].y + sa[3].y);
        t.z = (sa[0].z + sa[1].z) + (sa[2].z + sa[3].z);
        t.w = (sa[0].w + sa[1].w) + (sa[2].w + sa[3].w);

        if (h == 1) *(float4*)&sm.b.part[r][c4] = t;
        __syncthreads();
        if (h == 0) {
            const float4 p  = *(const float4*)&sm.b.part[r][c4];
            const float4 bb = *(const float4*)(bh + c4);
            *(float4*)&g_bow_h[(kb * K1_ROWS_PER_BLK + r) * HID + c4] =
                make_float4(lky(t.x + p.x + bb.x), lky(t.y + p.y + bb.y),
                            lky(t.z + p.z + bb.z), lky(t.w + p.w + bb.w));
        }
    }
}

// ============================================================================
// K3 v3: epilogue. 8 rows/block, 256 threads, grid (256, 2) = 512 blocks.
//   - We staged in smem in 2 chunks of 128 k (32 KB, unioned with reducers)
//   - thread = (row, 4 cols, kp) ; k-unroll 2 -> 4 independent FMA2 chains
// ============================================================================
#define EPB 8

union EpSmem {
    float WeS[128][64];                      // 32 KB weight stage
    struct {
        float red[2][EPB][64];               // 4 KB embd K-partials
        float predred[EPB * 10];             // pred K-partials
    } r;
};

__global__ __launch_bounds__(256) void epilogue_kernel(
    const float* __restrict__ We_bow, const float* __restrict__ be_bow,
    const float* __restrict__ Wp_bow, const float* __restrict__ bp_bow,
    const float* __restrict__ We_beo, const float* __restrict__ be_beo,
    const float* __restrict__ Wp_beo, const float* __restrict__ bp_beo,
    float* __restrict__ out)
{
    __shared__ float sh[EPB][HID];           // 8 KB H stage
    __shared__ EpSmem u;

    const int side = blockIdx.y;
    const int row0 = blockIdx.x * EPB;
    const int tid  = threadIdx.x;

    const float* H  = side ? g_beo_h : g_bow_h;
    const float* We = side ? We_beo : We_bow;
    const float* be = side ? be_beo : be_bow;
    const float* Wp = side ? Wp_beo : Wp_bow;
    const float* bp = side ? bp_beo : bp_bow;

    // stage H tile [8][256]: 512 float4 / 256 thr = 2 each
    #pragma unroll
    for (int f = tid; f < EPB * (HID / 4); f += 256) {
        int r = f >> 6, cq = f & 63;
        *(float4*)&sh[r][cq * 4] = *(const float4*)&H[(row0 + r) * HID + cq * 4];
    }

    const int cg  = tid & 15;          // 16 col groups * 4 cols
    const int row = (tid >> 4) & 7;    // 8 rows
    const int kp  = tid >> 7;          // K partition 0/1

    unsigned long long acc[4];
    acc[0] = acc[1] = acc[2] = acc[3] = 0ull;

    #pragma unroll
    for (int kc = 0; kc < 2; kc++) {
        // stage We rows [kc*128, +128): 2048 float4 / 256 thr = 8 each
        #pragma unroll
        for (int f = tid; f < 128 * 16; f += 256) {
            int kr = f >> 4, nq = f & 15;
            *(float4*)&u.WeS[kr][nq * 4] =
                *(const float4*)&We[(kc * 128 + kr) * 64 + nq * 4];
        }
        __syncthreads();

        const int kb = kp * 64;
        #pragma unroll 8
        for (int k = 0; k < 64; k += 2) {
            const int kk0 = kb + k, kk1 = kb + k + 1;
            float h0 = sh[row][kc * 128 + kk0];
            float h1 = sh[row][kc * 128 + kk1];
            unsigned long long w00 = *(const unsigned long long*)&u.WeS[kk0][cg * 4];
            unsigned long long w01 = *(const unsigned long long*)&u.WeS[kk0][cg * 4 + 2];
            unsigned long long w10 = *(const unsigned long long*)&u.WeS[kk1][cg * 4];
            unsigned long long w11 = *(const unsigned long long*)&u.WeS[kk1][cg * 4 + 2];
            unsigned long long ph0, ph1;
            asm("mov.b64 %0, {%1, %1};" : "=l"(ph0) : "f"(h0));
            asm("mov.b64 %0, {%1, %1};" : "=l"(ph1) : "f"(h1));
            asm("fma.rn.f32x2 %0, %1, %2, %0;" : "+l"(acc[0]) : "l"(ph0), "l"(w00));
            asm("fma.rn.f32x2 %0, %1, %2, %0;" : "+l"(acc[1]) : "l"(ph0), "l"(w01));
            asm("fma.rn.f32x2 %0, %1, %2, %0;" : "+l"(acc[2]) : "l"(ph1), "l"(w10));
            asm("fma.rn.f32x2 %0, %1, %2, %0;" : "+l"(acc[3]) : "l"(ph1), "l"(w11));
        }
        __syncthreads();   // done with this WeS chunk
    }

    // ---- store embd K-partials (union now safe to reuse) ----
    {
        float a0, a1, a2, a3, c0, c1, c2, c3;
        asm("mov.b64 {%0, %1}, %2;" : "=f"(a0), "=f"(a1) : "l"(acc[0]));
        asm("mov.b64 {%0, %1}, %2;" : "=f"(a2), "=f"(a3) : "l"(acc[1]));
        asm("mov.b64 {%0, %1}, %2;" : "=f"(c0), "=f"(c1) : "l"(acc[2]));
        asm("mov.b64 {%0, %1}, %2;" : "=f"(c2), "=f"(c3) : "l"(acc[3]));
        *(float4*)&u.r.red[kp][row][cg * 4] =
            make_float4(a0 + c0, a1 + c1, a2 + c2, a3 + c3);
    }

    // ---- pred K-partials: 80 threads, 4 independent chains each ----
    if (tid < EPB * 10) {
        int r   = tid / 10;
        int rem = tid - r * 10;
        int j   = rem % 5;
        int kq  = rem / 5;
        const int kb = kq * 128;
        float a0 = 0.f, a1 = 0.f, a2 = 0.f, a3 = 0.f;
        #pragma unroll 4
        for (int k = 0; k < 128; k += 4) {
            a0 = fmaf(sh[r][kb + k + 0], Wp[(kb + k + 0) * 5 + j], a0);
            a1 = fmaf(sh[r][kb + k + 1], Wp[(kb + k + 1) * 5 + j], a1);
            a2 = fmaf(sh[r][kb + k + 2], Wp[(kb + k + 2) * 5 + j], a2);
            a3 = fmaf(sh[r][kb + k + 3], Wp[(kb + k + 3) * 5 + j], a3);
        }
        u.r.predred[tid] = (a0 + a1) + (a2 + a3);
    }
    __syncthreads();

    // ---- final combine + store ----
    if (tid < EPB * 16) {
        const int rr = tid >> 4;
        const int c4 = (tid & 15) * 4;
        float4 p0 = *(const float4*)&u.r.red[0][rr][c4];
        float4 p1 = *(const float4*)&u.r.red[1][rr][c4];
        float4 bbv = *(const float4*)&be[c4];
        const int ebase = side ? (BATCH * 64) : 0;
        *(float4*)&out[ebase + (row0 + rr) * 64 + c4] =
            make_float4(p0.x + p1.x + bbv.x, p0.y + p1.y + bbv.y,
                        p0.z + p1.z + bbv.z, p0.w + p1.w + bbv.w);
    }
    if (tid < EPB * 5) {
        int r = tid / 5, j = tid - r * 5;
        float v = u.r.predred[r * 10 + j] + u.r.predred[r * 10 + 5 + j] + bp[j];
        const int pbase = BATCH * 128 + (side ? BATCH * 5 : 0);
        out[pbase + (row0 + r) * 5 + j] = v;
    }
}

// ============================================================================
extern "C" void kernel_launch(void* const* d_in, const int* in_sizes, int n_in,
                              void* d_out, int out_size)
{
    const unsigned int* s_words = (const unsigned int*)d_in[0];
    const float* x        = (const float*)d_in[1];
    const float* W_bow_h  = (const float*)d_in[2];
    const float* b_bow_h  = (const float*)d_in[3];
    const float* W_bow_p  = (const float*)d_in[4];
    const float* b_bow_p  = (const float*)d_in[5];
    const float* W_bow_e  = (const float*)d_in[6];
    const float* b_bow_e  = (const float*)d_in[7];
    const float* W_beo_h  = (const float*)d_in[8];
    const float* b_beo_h  = (const float*)d_in[9];
    const float* W_beo_p  = (const float*)d_in[10];
    const float* b_beo_p  = (const float*)d_in[11];
    const float* W_beo_e  = (const float*)d_in[12];
    const float* b_beo_e  = (const float*)d_in[13];
    float* out = (float*)d_out;

    fused_hidden_kernel<<<K2_BLOCKS + K1_BLOCKS, 256>>>(
        s_words, W_bow_h, b_bow_h, x, W_beo_h, b_beo_h);

    dim3 g3(BATCH / EPB, 2);
    epilogue_kernel<<<g3, 256>>>(W_bow_e, b_bow_e, W_bow_p, b_bow_p,
                                 W_beo_e, b_beo_e, W_beo_p, b_beo_p, out);
}

// round 7
// speedup vs baseline: 2.2647x; 1.2000x over previous
#include <cuda_runtime.h>

#define VOCAB 100000
#define BATCH 2048
#define SEQ   50
#define HID   256
#define KIN   512

// ---------------- scratch (device globals; no allocation allowed) ----------
__device__ float g_bow_h[BATCH * HID];
__device__ float g_beo_h[BATCH * HID];

__device__ __forceinline__ float lky(float v) {
    return (v > 0.f) ? v : 0.2f * v;
}

// ============================================================================
// Fused kernel: blocks [0, K2_BLOCKS) do the beo GEMM; blocks
// [K2_BLOCKS, K2_BLOCKS + K1_BLOCKS) do the bow gather. 256 threads each.
// ============================================================================
#define BM 64
#define BN 64
#define BK 32
#define K2_BLOCKS ((BATCH / BM) * (HID / BN))   // 128
#define K1_ROWS_PER_BLK 2
#define K1_BLOCKS (BATCH / K1_ROWS_PER_BLK)     // 1024

union SmemU {
    struct {                       // GEMM tiles
        float As[BM][BK + 4];
        float Bs[BK][BN];
    } g;
    struct {                       // bow gather scratch
        unsigned int wbuf[K1_ROWS_PER_BLK * SEQ];
        int   toks[K1_ROWS_PER_BLK][SEQ];
        float keep[K1_ROWS_PER_BLK][SEQ];
        float part[K1_ROWS_PER_BLK][HID];
        int   is64;
    } b;
};

__global__ __launch_bounds__(256) void fused_hidden_kernel(
    const unsigned int* __restrict__ s_words,
    const float* __restrict__ Wh,    const float* __restrict__ bh,
    const float* __restrict__ X,     const float* __restrict__ W,
    const float* __restrict__ bias)
{
    __shared__ SmemU sm;
    const int tid = threadIdx.x;

    if (blockIdx.x < K2_BLOCKS) {
        // ------------------------- beo GEMM path ---------------------------
        const int bx = blockIdx.x;
        const int m0 = (bx >> 2) * BM;
        const int n0 = (bx & 3) * BN;
        const int tx = tid & 15;
        const int ty = tid >> 4;

        unsigned long long acc[4][2];
        #pragma unroll
        for (int r = 0; r < 4; r++) { acc[r][0] = 0ull; acc[r][1] = 0ull; }

        for (int k0 = 0; k0 < KIN; k0 += BK) {
            #pragma unroll
            for (int f = tid; f < BM * BK / 4; f += 256) {
                int r = f >> 3, q = f & 7;
                *(float4*)&sm.g.As[r][q * 4] =
                    *(const float4*)&X[(m0 + r) * KIN + k0 + q * 4];
            }
            #pragma unroll
            for (int f = tid; f < BK * BN / 4; f += 256) {
                int kr = f >> 4, nq = f & 15;
                *(float4*)&sm.g.Bs[kr][nq * 4] =
                    *(const float4*)&W[(k0 + kr) * HID + n0 + nq * 4];
            }
            __syncthreads();

            #pragma unroll
            for (int k = 0; k < BK; k++) {
                float4 bv = *(const float4*)&sm.g.Bs[k][tx * 4];
                unsigned long long pb0, pb1;
                asm("mov.b64 %0, {%1, %2};" : "=l"(pb0) : "f"(bv.x), "f"(bv.y));
                asm("mov.b64 %0, {%1, %2};" : "=l"(pb1) : "f"(bv.z), "f"(bv.w));
                #pragma unroll
                for (int r = 0; r < 4; r++) {
                    float av = sm.g.As[ty * 4 + r][k];
                    unsigned long long pa;
                    asm("mov.b64 %0, {%1, %1};" : "=l"(pa) : "f"(av));
                    asm("fma.rn.f32x2 %0, %1, %2, %0;" : "+l"(acc[r][0]) : "l"(pa), "l"(pb0));
                    asm("fma.rn.f32x2 %0, %1, %2, %0;" : "+l"(acc[r][1]) : "l"(pa), "l"(pb1));
                }
            }
            __syncthreads();
        }

        const float4 bb = *(const float4*)&bias[n0 + tx * 4];
        #pragma unroll
        for (int r = 0; r < 4; r++) {
            float o0, o1, o2, o3;
            asm("mov.b64 {%0, %1}, %2;" : "=f"(o0), "=f"(o1) : "l"(acc[r][0]));
            asm("mov.b64 {%0, %1}, %2;" : "=f"(o2), "=f"(o3) : "l"(acc[r][1]));
            *(float4*)&g_beo_h[(m0 + ty * 4 + r) * HID + n0 + tx * 4] =
                make_float4(lky(o0 + bb.x), lky(o1 + bb.y),
                            lky(o2 + bb.z), lky(o3 + bb.w));
        }
    } else {
        // ------------------------- bow gather path -------------------------
        const int kb    = blockIdx.x - K2_BLOCKS;
        const int wbase = kb * (K1_ROWS_PER_BLK * SEQ);

        if (tid < K1_ROWS_PER_BLK * SEQ) sm.b.wbuf[tid] = s_words[wbase + tid];
        __syncthreads();

        if (tid == 0) {
            int all0 = 1;
            #pragma unroll
            for (int i = 1; i < K1_ROWS_PER_BLK * SEQ; i += 2)
                all0 &= (sm.b.wbuf[i] == 0u);
            sm.b.is64 = all0;
        }
        __syncthreads();

        const int is64 = sm.b.is64;
        if (tid < K1_ROWS_PER_BLK * SEQ) {
            int r = tid / SEQ, j = tid - r * SEQ;
            sm.b.toks[r][j] = is64 ? (int)s_words[2 * (wbase + tid)]
                                   : (int)sm.b.wbuf[tid];
        }
        __syncthreads();

        if (tid < K1_ROWS_PER_BLK * SEQ) {
            int r = tid / SEQ, j = tid - r * SEQ;
            int t = sm.b.toks[r][j];
            float k = 1.0f;
            for (int j2 = 0; j2 < j; j2++)
                if (sm.b.toks[r][j2] == t) { k = 0.0f; break; }
            sm.b.keep[r][j] = k;
        }
        __syncthreads();

        // gather: 2 rows x 2 halves x 64 col-threads; 8-deep load batches
        const int r    = tid >> 7;
        const int h    = (tid >> 6) & 1;
        const int c4   = (tid & 63) * 4;
        const int jb   = h * (SEQ / 2);       // 25 tokens per half
        const float* __restrict__ Wc = Wh + c4;

        float4 sa[8];
        #pragma unroll
        for (int q = 0; q < 8; q++) sa[q] = make_float4(0.f, 0.f, 0.f, 0.f);

        #pragma unroll
        for (int i = 0; i < 24; i += 8) {
            float4 v[8];
            float  kf[8];
            #pragma unroll
            for (int q = 0; q < 8; q++) {
                v[q]  = *(const float4*)(Wc + sm.b.toks[r][jb + i + q] * HID);
                kf[q] = sm.b.keep[r][jb + i + q];
            }
            #pragma unroll
            for (int q = 0; q < 8; q++) {
                sa[q].x = fmaf(kf[q], v[q].x, sa[q].x);
                sa[q].y = fmaf(kf[q], v[q].y, sa[q].y);
                sa[q].z = fmaf(kf[q], v[q].z, sa[q].z);
                sa[q].w = fmaf(kf[q], v[q].w, sa[q].w);
            }
        }
        {   // tail token (i = 24)
            const float4 v = *(const float4*)(Wc + sm.b.toks[r][jb + 24] * HID);
            const float kf = sm.b.keep[r][jb + 24];
            sa[0].x = fmaf(kf, v.x, sa[0].x); sa[0].y = fmaf(kf, v.y, sa[0].y);
            sa[0].z = fmaf(kf, v.z, sa[0].z); sa[0].w = fmaf(kf, v.w, sa[0].w);
        }

        float4 t;
        t.x = ((sa[0].x + sa[1].x) + (sa[2].x + sa[3].x)) +
              ((sa[4].x + sa[5].x) + (sa[6].x + sa[7].x));
        t.y = ((sa[0].y + sa[1].y) + (sa[2].y + sa[3].y)) +
              ((sa[4].y + sa[5].y) + (sa[6].y + sa[7].y));
        t.z = ((sa[0].z + sa[1].z) + (sa[2].z + sa[3].z)) +
              ((sa[4].z + sa[5].z) + (sa[6].z + sa[7].z));
        t.w = ((sa[0].w + sa[1].w) + (sa[2].w + sa[3].w)) +
              ((sa[4].w + sa[5].w) + (sa[6].w + sa[7].w));

        if (h == 1) *(float4*)&sm.b.part[r][c4] = t;
        __syncthreads();
        if (h == 0) {
            const float4 p  = *(const float4*)&sm.b.part[r][c4];
            const float4 bb = *(const float4*)(bh + c4);
            *(float4*)&g_bow_h[(kb * K1_ROWS_PER_BLK + r) * HID + c4] =
                make_float4(lky(t.x + p.x + bb.x), lky(t.y + p.y + bb.y),
                            lky(t.z + p.z + bb.z), lky(t.w + p.w + bb.w));
        }
    }
}

// ============================================================================
// K3 v4: epilogue. EPB=16 rows/block, 256 threads, grid (128, 2).
//   - H staged TRANSPOSED: sh_t[k][row] (stride 20 -> LDS.128-aligned)
//   - We staged in 2 chunks of 128 k (32 KB)
//   - thread tile 4 rows x 4 cols x K-split-4: per k, 2x LDS.128 -> 8 FMA2
// ============================================================================
#define EPB 16
#define HP  20                                  // padded row stride (floats)

union EpSmem {
    float WeS[128][64];                         // 32 KB weight stage
    struct {
        float red[4][EPB][64];                  // 16 KB embd K-partials
        float predred[EPB * 10];                // pred K-partials
    } r;
};

__global__ __launch_bounds__(256) void epilogue_kernel(
    const float* __restrict__ We_bow, const float* __restrict__ be_bow,
    const float* __restrict__ Wp_bow, const float* __restrict__ bp_bow,
    const float* __restrict__ We_beo, const float* __restrict__ be_beo,
    const float* __restrict__ Wp_beo, const float* __restrict__ bp_beo,
    float* __restrict__ out)
{
    __shared__ __align__(16) float sh_t[HID][HP];   // 20 KB transposed H
    __shared__ EpSmem u;

    const int side = blockIdx.y;
    const int row0 = blockIdx.x * EPB;
    const int tid  = threadIdx.x;

    const float* H  = side ? g_beo_h : g_bow_h;
    const float* We = side ? We_beo : We_bow;
    const float* be = side ? be_beo : be_bow;
    const float* Wp = side ? Wp_beo : Wp_bow;
    const float* bp = side ? bp_beo : bp_bow;

    // stage H transposed: f -> (row = f&15, colquad = f>>4); 1024 float4
    #pragma unroll
    for (int f = tid; f < EPB * (HID / 4); f += 256) {
        int r = f & 15, cq = f >> 4;
        float4 v = *(const float4*)&H[(row0 + r) * HID + cq * 4];
        sh_t[cq * 4 + 0][r] = v.x;
        sh_t[cq * 4 + 1][r] = v.y;
        sh_t[cq * 4 + 2][r] = v.z;
        sh_t[cq * 4 + 3][r] = v.w;
    }

    const int cg = tid & 15;           // 16 col groups * 4 cols
    const int rg = (tid >> 4) & 3;     // 4 row groups * 4 rows
    const int kp = tid >> 6;           // 4 K partitions (32 k per chunk each)

    unsigned long long acc[4][2];
    #pragma unroll
    for (int r = 0; r < 4; r++) { acc[r][0] = 0ull; acc[r][1] = 0ull; }

    #pragma unroll
    for (int kc = 0; kc < 2; kc++) {
        // stage We rows [kc*128, +128): 2048 float4 / 256 thr = 8 each
        #pragma unroll
        for (int f = tid; f < 128 * 16; f += 256) {
            int kr = f >> 4, nq = f & 15;
            *(float4*)&u.WeS[kr][nq * 4] =
                *(const float4*)&We[(kc * 128 + kr) * 64 + nq * 4];
        }
        __syncthreads();

        #pragma unroll 8
        for (int k = 0; k < 32; k++) {
            const int kk = kp * 32 + k;            // row within WeS chunk
            const int kg = kc * 128 + kk;          // global k
            float4 hv = *(const float4*)&sh_t[kg][rg * 4];
            float4 wv = *(const float4*)&u.WeS[kk][cg * 4];
            unsigned long long pw0, pw1;
            asm("mov.b64 %0, {%1, %2};" : "=l"(pw0) : "f"(wv.x), "f"(wv.y));
            asm("mov.b64 %0, {%1, %2};" : "=l"(pw1) : "f"(wv.z), "f"(wv.w));
            unsigned long long ph0, ph1, ph2, ph3;
            asm("mov.b64 %0, {%1, %1};" : "=l"(ph0) : "f"(hv.x));
            asm("mov.b64 %0, {%1, %1};" : "=l"(ph1) : "f"(hv.y));
            asm("mov.b64 %0, {%1, %1};" : "=l"(ph2) : "f"(hv.z));
            asm("mov.b64 %0, {%1, %1};" : "=l"(ph3) : "f"(hv.w));
            asm("fma.rn.f32x2 %0, %1, %2, %0;" : "+l"(acc[0][0]) : "l"(ph0), "l"(pw0));
            asm("fma.rn.f32x2 %0, %1, %2, %0;" : "+l"(acc[0][1]) : "l"(ph0), "l"(pw1));
            asm("fma.rn.f32x2 %0, %1, %2, %0;" : "+l"(acc[1][0]) : "l"(ph1), "l"(pw0));
            asm("fma.rn.f32x2 %0, %1, %2, %0;" : "+l"(acc[1][1]) : "l"(ph1), "l"(pw1));
            asm("fma.rn.f32x2 %0, %1, %2, %0;" : "+l"(acc[2][0]) : "l"(ph2), "l"(pw0));
            asm("fma.rn.f32x2 %0, %1, %2, %0;" : "+l"(acc[2][1]) : "l"(ph2), "l"(pw1));
            asm("fma.rn.f32x2 %0, %1, %2, %0;" : "+l"(acc[3][0]) : "l"(ph3), "l"(pw0));
            asm("fma.rn.f32x2 %0, %1, %2, %0;" : "+l"(acc[3][1]) : "l"(ph3), "l"(pw1));
        }
        __syncthreads();   // done with this WeS chunk
    }

    // ---- store embd K-partials (union now safe to reuse) ----
    #pragma unroll
    for (int r = 0; r < 4; r++) {
        float a0, a1, a2, a3;
        asm("mov.b64 {%0, %1}, %2;" : "=f"(a0), "=f"(a1) : "l"(acc[r][0]));
        asm("mov.b64 {%0, %1}, %2;" : "=f"(a2), "=f"(a3) : "l"(acc[r][1]));
        *(float4*)&u.r.red[kp][rg * 4 + r][cg * 4] = make_float4(a0, a1, a2, a3);
    }

    // ---- pred K-partials: 160 threads, 4 independent chains each ----
    if (tid < EPB * 10) {
        int r   = tid / 10;
        int rem = tid - r * 10;
        int j   = rem % 5;
        int kq  = rem / 5;
        const int kb = kq * 128;
        float a0 = 0.f, a1 = 0.f, a2 = 0.f, a3 = 0.f;
        #pragma unroll 4
        for (int k = 0; k < 128; k += 4) {
            a0 = fmaf(sh_t[kb + k + 0][r], Wp[(kb + k + 0) * 5 + j], a0);
            a1 = fmaf(sh_t[kb + k + 1][r], Wp[(kb + k + 1) * 5 + j], a1);
            a2 = fmaf(sh_t[kb + k + 2][r], Wp[(kb + k + 2) * 5 + j], a2);
            a3 = fmaf(sh_t[kb + k + 3][r], Wp[(kb + k + 3) * 5 + j], a3);
        }
        u.r.predred[tid] = (a0 + a1) + (a2 + a3);
    }
    __syncthreads();

    // ---- final combine + store ----
    {
        const int rr = tid >> 4;
        const int c4 = (tid & 15) * 4;
        float4 p0 = *(const float4*)&u.r.red[0][rr][c4];
        float4 p1 = *(const float4*)&u.r.red[1][rr][c4];
        float4 p2 = *(const float4*)&u.r.red[2][rr][c4];
        float4 p3 = *(const float4*)&u.r.red[3][rr][c4];
        float4 bbv = *(const float4*)&be[c4];
        const int ebase = side ? (BATCH * 64) : 0;
        *(float4*)&out[ebase + (row0 + rr) * 64 + c4] =
            make_float4((p0.x + p1.x) + (p2.x + p3.x) + bbv.x,
                        (p0.y + p1.y) + (p2.y + p3.y) + bbv.y,
                        (p0.z + p1.z) + (p2.z + p3.z) + bbv.z,
                        (p0.w + p1.w) + (p2.w + p3.w) + bbv.w);
    }
    if (tid < EPB * 5) {
        int r = tid / 5, j = tid - r * 5;
        float v = u.r.predred[r * 10 + j] + u.r.predred[r * 10 + 5 + j] + bp[j];
        const int pbase = BATCH * 128 + (side ? BATCH * 5 : 0);
        out[pbase + (row0 + r) * 5 + j] = v;
    }
}

// ============================================================================
extern "C" void kernel_launch(void* const* d_in, const int* in_sizes, int n_in,
                              void* d_out, int out_size)
{
    const unsigned int* s_words = (const unsigned int*)d_in[0];
    const float* x        = (const float*)d_in[1];
    const float* W_bow_h  = (const float*)d_in[2];
    const float* b_bow_h  = (const float*)d_in[3];
    const float* W_bow_p  = (const float*)d_in[4];
    const float* b_bow_p  = (const float*)d_in[5];
    const float* W_bow_e  = (const float*)d_in[6];
    const float* b_bow_e  = (const float*)d_in[7];
    const float* W_beo_h  = (const float*)d_in[8];
    const float* b_beo_h  = (const float*)d_in[9];
    const float* W_beo_p  = (const float*)d_in[10];
    const float* b_beo_p  = (const float*)d_in[11];
    const float* W_beo_e  = (const float*)d_in[12];
    const float* b_beo_e  = (const float*)d_in[13];
    float* out = (float*)d_out;

    fused_hidden_kernel<<<K2_BLOCKS + K1_BLOCKS, 256>>>(
        s_words, W_bow_h, b_bow_h, x, W_beo_h, b_beo_h);

    dim3 g3(BATCH / EPB, 2);
    epilogue_kernel<<<g3, 256>>>(W_bow_e, b_bow_e, W_bow_p, b_bow_p,
                                 W_beo_e, b_beo_e, W_beo_p, b_beo_p, out);
}